// round 1
// baseline (speedup 1.0000x reference)
#include <cuda_runtime.h>
#include <cstdio>

#define EDIM 1024
#define HHEADS 16
#define DHEAD 64
#define RRANK 8
#define TLEN 1024
#define BBATCH 8
#define SLEN 1024

static constexpr float SCALE = 0.125f;  // D^-0.5

// ---------------- scratch (static device arrays; no allocation) -------------
__device__ float g_wq[EDIM * EDIM];            //  4 MB
__device__ float g_wkv[2 * EDIM * EDIM];       //  8 MB
__device__ float g_wo[EDIM * EDIM];            //  4 MB
__device__ float g_q[TLEN * BBATCH * EDIM];    // 32 MB  (T,B,E), already scaled
__device__ float g_kv[SLEN * BBATCH * 2 * EDIM]; // 64 MB (S,B,2E)
__device__ float g_ctx[TLEN * BBATCH * EDIM];  // 32 MB  (T,B,E)

// ---------------- kernel 1: materialize factorized weights ------------------
// wq  = in_proj_weight_q  @ tgt_factor   (E*E)
// wkv = in_proj_weight_kv @ src_factor   (2E*E)
// wo  = out_proj_weight   @ tgt_factor   (E*E)
__global__ void build_weights_kernel(const float* __restrict__ wq_f,
                                     const float* __restrict__ wkv_f,
                                     const float* __restrict__ wo_f,
                                     const float* __restrict__ tgt,
                                     const float* __restrict__ src) {
    int n = blockIdx.x * blockDim.x + threadIdx.x;
    const int NQ = EDIM * EDIM;
    const int NKV = 2 * EDIM * EDIM;
    float tf[RRANK], sf[RRANK];
#pragma unroll
    for (int r = 0; r < RRANK; r++) { tf[r] = tgt[r]; sf[r] = src[r]; }

    if (n < NQ) {
        const float* w = wq_f + (size_t)n * RRANK;
        float acc = 0.f;
#pragma unroll
        for (int r = 0; r < RRANK; r++) acc += w[r] * tf[r];
        g_wq[n] = acc;
    } else if (n < NQ + NKV) {
        int m = n - NQ;
        const float* w = wkv_f + (size_t)m * RRANK;
        float acc = 0.f;
#pragma unroll
        for (int r = 0; r < RRANK; r++) acc += w[r] * sf[r];
        g_wkv[m] = acc;
    } else if (n < NQ + NKV + NQ) {
        int m = n - NQ - NKV;
        const float* w = wo_f + (size_t)m * RRANK;
        float acc = 0.f;
#pragma unroll
        for (int r = 0; r < RRANK; r++) acc += w[r] * tf[r];
        g_wo[m] = acc;
    }
}

// ---------------- kernel 2: SGEMM  C[M,N] = alpha * A[M,K] @ B[N,K]^T -------
// Classic 128x128 tile, BK=16, 256 threads, 8x8 per-thread micro-tile.
// All problem dims divide the tile sizes; no bounds checks.
__global__ __launch_bounds__(256) void sgemm_abt_kernel(
    const float* __restrict__ A, const float* __restrict__ B,
    float* __restrict__ C, int M, int N, int K, float alpha) {
    __shared__ float As[16][128];
    __shared__ float Bs[16][128];

    const int tid = threadIdx.x;
    const int m0 = blockIdx.y * 128;
    const int n0 = blockIdx.x * 128;

    const int lrow = tid >> 2;          // 0..63
    const int lcol = (tid & 3) * 4;     // 0,4,8,12
    const int ty = tid >> 4;            // 0..15
    const int tx = tid & 15;            // 0..15

    float acc[8][8];
#pragma unroll
    for (int i = 0; i < 8; i++)
#pragma unroll
        for (int j = 0; j < 8; j++) acc[i][j] = 0.f;

    for (int k0 = 0; k0 < K; k0 += 16) {
        __syncthreads();
#pragma unroll
        for (int i = 0; i < 2; i++) {
            int row = lrow + i * 64;
            float4 av = *reinterpret_cast<const float4*>(
                A + (size_t)(m0 + row) * K + k0 + lcol);
            As[lcol + 0][row] = av.x;
            As[lcol + 1][row] = av.y;
            As[lcol + 2][row] = av.z;
            As[lcol + 3][row] = av.w;
            float4 bv = *reinterpret_cast<const float4*>(
                B + (size_t)(n0 + row) * K + k0 + lcol);
            Bs[lcol + 0][row] = bv.x;
            Bs[lcol + 1][row] = bv.y;
            Bs[lcol + 2][row] = bv.z;
            Bs[lcol + 3][row] = bv.w;
        }
        __syncthreads();
#pragma unroll
        for (int k = 0; k < 16; k++) {
            float a[8], b[8];
            const float4* ap = reinterpret_cast<const float4*>(&As[k][ty * 8]);
            const float4* bp = reinterpret_cast<const float4*>(&Bs[k][tx * 8]);
            float4 a0 = ap[0], a1 = ap[1];
            float4 b0 = bp[0], b1 = bp[1];
            a[0]=a0.x; a[1]=a0.y; a[2]=a0.z; a[3]=a0.w;
            a[4]=a1.x; a[5]=a1.y; a[6]=a1.z; a[7]=a1.w;
            b[0]=b0.x; b[1]=b0.y; b[2]=b0.z; b[3]=b0.w;
            b[4]=b1.x; b[5]=b1.y; b[6]=b1.z; b[7]=b1.w;
#pragma unroll
            for (int i = 0; i < 8; i++)
#pragma unroll
                for (int j = 0; j < 8; j++) acc[i][j] += a[i] * b[j];
        }
    }

#pragma unroll
    for (int i = 0; i < 8; i++) {
        float* crow = C + (size_t)(m0 + ty * 8 + i) * N + n0 + tx * 8;
        float4 v0 = make_float4(alpha * acc[i][0], alpha * acc[i][1],
                                alpha * acc[i][2], alpha * acc[i][3]);
        float4 v1 = make_float4(alpha * acc[i][4], alpha * acc[i][5],
                                alpha * acc[i][6], alpha * acc[i][7]);
        reinterpret_cast<float4*>(crow)[0] = v0;
        reinterpret_cast<float4*>(crow)[1] = v1;
    }
}

// ---------------- kernel 3: flash attention (fp32 SIMT) ---------------------
// grid: (T/128, B*H). block: 128 threads. One thread = one query row.
// K/V tiles of 32 keys live in shared; score reads broadcast across the block.
__global__ __launch_bounds__(128) void attn_kernel(
    const float* __restrict__ qg, const float* __restrict__ kvg,
    const unsigned char* __restrict__ mask, float* __restrict__ ctx) {
    __shared__ float4 Ks[32][16];   // 32 keys x 64 floats
    __shared__ float4 Vs[32][16];
    __shared__ float sbias[32];

    const int bh = blockIdx.y;
    const int b = bh >> 4;          // / HHEADS
    const int h = bh & 15;          // % HHEADS
    const int t = blockIdx.x * 128 + threadIdx.x;

    const float* qrow = qg + ((size_t)t * BBATCH + b) * EDIM + h * DHEAD;
    float4 qv[16];
#pragma unroll
    for (int c = 0; c < 16; c++)
        qv[c] = reinterpret_cast<const float4*>(qrow)[c];

    float4 ov[16];
#pragma unroll
    for (int c = 0; c < 16; c++) ov[c] = make_float4(0.f, 0.f, 0.f, 0.f);
    float mrow = -1e30f, lrow = 0.f;

    for (int s0 = 0; s0 < SLEN; s0 += 32) {
        __syncthreads();
#pragma unroll
        for (int i = 0; i < 4; i++) {
            int lin = threadIdx.x + i * 128;
            int row = lin >> 4;
            int col = lin & 15;
            const float* kbase =
                kvg + ((size_t)(s0 + row) * BBATCH + b) * (2 * EDIM) + h * DHEAD;
            Ks[row][col] = reinterpret_cast<const float4*>(kbase)[col];
            Vs[row][col] = reinterpret_cast<const float4*>(kbase + EDIM)[col];
        }
        if (threadIdx.x < 32)
            sbias[threadIdx.x] =
                mask[b * SLEN + s0 + threadIdx.x] ? -1e30f : 0.f;
        __syncthreads();

        float sc[32];
        float mt = mrow;
#pragma unroll
        for (int j = 0; j < 32; j++) {
            float a = 0.f;
#pragma unroll
            for (int c = 0; c < 16; c++) {
                float4 k4 = Ks[j][c];
                float4 q4 = qv[c];
                a += q4.x * k4.x;
                a += q4.y * k4.y;
                a += q4.z * k4.z;
                a += q4.w * k4.w;
            }
            a += sbias[j];
            sc[j] = a;
            mt = fmaxf(mt, a);
        }
        float corr = __expf(mrow - mt);
        lrow *= corr;
#pragma unroll
        for (int c = 0; c < 16; c++) {
            ov[c].x *= corr; ov[c].y *= corr;
            ov[c].z *= corr; ov[c].w *= corr;
        }
#pragma unroll
        for (int j = 0; j < 32; j++) {
            float p = __expf(sc[j] - mt);
            lrow += p;
#pragma unroll
            for (int c = 0; c < 16; c++) {
                float4 v4 = Vs[j][c];
                ov[c].x += p * v4.x;
                ov[c].y += p * v4.y;
                ov[c].z += p * v4.z;
                ov[c].w += p * v4.w;
            }
        }
        mrow = mt;
    }

    float inv = 1.f / lrow;
    float* crow = ctx + ((size_t)t * BBATCH + b) * EDIM + h * DHEAD;
#pragma unroll
    for (int c = 0; c < 16; c++) {
        float4 o = ov[c];
        o.x *= inv; o.y *= inv; o.z *= inv; o.w *= inv;
        reinterpret_cast<float4*>(crow)[c] = o;
    }
}

// ---------------- launch ----------------------------------------------------
extern "C" void kernel_launch(void* const* d_in, const int* in_sizes, int n_in,
                              void* d_out, int out_size) {
    const float* query = (const float*)d_in[0];          // (T,B,E)
    const float* key   = (const float*)d_in[1];          // (S,B,E)
    const float* tgt   = (const float*)d_in[2];          // (R,)
    const float* src   = (const float*)d_in[3];          // (R,)
    const float* wq_f  = (const float*)d_in[4];          // (E*E, R)
    const float* wkv_f = (const float*)d_in[5];          // (2E*E, R)
    const float* wo_f  = (const float*)d_in[6];          // (E*E, R)
    const unsigned char* mask = (const unsigned char*)d_in[7]; // (B,S) bool
    float* out = (float*)d_out;                          // (T,B,E)

    float *wq, *wkv, *wo, *q, *kv, *ctx;
    cudaGetSymbolAddress((void**)&wq, g_wq);
    cudaGetSymbolAddress((void**)&wkv, g_wkv);
    cudaGetSymbolAddress((void**)&wo, g_wo);
    cudaGetSymbolAddress((void**)&q, g_q);
    cudaGetSymbolAddress((void**)&kv, g_kv);
    cudaGetSymbolAddress((void**)&ctx, g_ctx);

    // 1. materialize weights (4M outputs)
    {
        int total = 4 * EDIM * EDIM;
        build_weights_kernel<<<(total + 255) / 256, 256>>>(wq_f, wkv_f, wo_f,
                                                           tgt, src);
    }

    const int M = TLEN * BBATCH;  // 8192

    // 2. q = query @ wq^T * SCALE    (8192 x 1024 x 1024)
    {
        dim3 grid(EDIM / 128, M / 128);
        sgemm_abt_kernel<<<grid, 256>>>(query, wq, q, M, EDIM, EDIM, SCALE);
    }

    // 3. kv = key @ wkv^T            (8192 x 2048 x 1024)
    {
        dim3 grid(2 * EDIM / 128, M / 128);
        sgemm_abt_kernel<<<grid, 256>>>(key, wkv, kv, M, 2 * EDIM, EDIM, 1.0f);
    }

    // 4. attention -> ctx (T,B,E)
    {
        dim3 grid(TLEN / 128, BBATCH * HHEADS);
        attn_kernel<<<grid, 128>>>(q, kv, mask, ctx);
    }

    // 5. out = ctx @ wo^T            (8192 x 1024 x 1024)
    {
        dim3 grid(EDIM / 128, M / 128);
        sgemm_abt_kernel<<<grid, 256>>>(ctx, wo, out, M, EDIM, EDIM, 1.0f);
    }
}